// round 7
// baseline (speedup 1.0000x reference)
#include <cuda_runtime.h>

#define IN_DIM  4096
#define OUT_DIM 4096
#define BATCH   16384
#define THREADS 1024
#define CPT     4              // columns per thread (OUT_DIM / THREADS)
#define RG      4              // rows per group (interleaved in smem)
#define GROUPS  4
#define ROWS_PER_BLOCK (RG * GROUPS)   // 16
#define SMEM_BYTES (2 * IN_DIM * RG * 4)   // double-buffered 2 x 64KB

// Packed per-output-column parameters (filled by precompute kernel)
__device__ float4   g_coef[OUT_DIM];
__device__ unsigned g_idxp[OUT_DIM];   // idx_a | (idx_b << 16)

// GATE_COEFS (16 gates x 4 coefficients)
__constant__ float G[16][4] = {
    {0, 0, 0, 0},  {0, 0, 0, 1},  {0, 1, 0,-1},  {0, 1, 0, 0},
    {0, 0, 1,-1},  {0, 0, 1, 0},  {0, 1, 1,-2},  {0, 1, 1,-1},
    {1,-1,-1, 1},  {1,-1,-1, 2},  {1, 0,-1, 0},  {1, 0,-1, 1},
    {1,-1, 0, 0},  {1,-1, 0, 1},  {1, 0, 0,-1},  {1, 0, 0, 0}
};

// idx buffers may be int32 or int64 depending on the harness's JAX x64 config.
// For int64-encoded indices in [0, IN_DIM), every odd 32-bit word is zero.
// For int32, odd words are random indices (all-zero probability ~ (1/4096)^4).
__device__ __forceinline__ int read_idx(const int* p32, int j, bool is64)
{
    return is64 ? p32[2 * j] : p32[j];
}

__global__ void precompute_kernel(const float* __restrict__ w,
                                  const int* __restrict__ ia32,
                                  const int* __restrict__ ib32)
{
    int j = blockIdx.x * blockDim.x + threadIdx.x;
    if (j >= OUT_DIM) return;

    const bool ia_is64 = ((ia32[1] | ia32[3] | ia32[5] | ia32[7]) == 0);
    const bool ib_is64 = ((ib32[1] | ib32[3] | ib32[5] | ib32[7]) == 0);

    float wv[16];
    float m = -1e30f;
#pragma unroll
    for (int k = 0; k < 16; k++) { wv[k] = w[j * 16 + k]; m = fmaxf(m, wv[k]); }
    float s = 0.f;
#pragma unroll
    for (int k = 0; k < 16; k++) { wv[k] = __expf(wv[k] - m); s += wv[k]; }
    float inv = 1.0f / s;
    float c0 = 0.f, c1 = 0.f, c2 = 0.f, c3 = 0.f;
#pragma unroll
    for (int k = 0; k < 16; k++) {
        float p = wv[k] * inv;
        c0 += p * G[k][0];
        c1 += p * G[k][1];
        c2 += p * G[k][2];
        c3 += p * G[k][3];
    }
    g_coef[j] = make_float4(c0, c1, c2, c3);

    unsigned a = (unsigned)read_idx(ia32, j, ia_is64) & (IN_DIM - 1);
    unsigned b = (unsigned)read_idx(ib32, j, ib_is64) & (IN_DIM - 1);
    g_idxp[j] = a | (b << 16);
}

__global__ __launch_bounds__(THREADS, 1)
void logic_kernel(const float* __restrict__ x, float* __restrict__ y)
{
    // Dynamic smem: two 4-row interleaved buffers.
    // Buffer layout: float4 at word-index c = (x[r0][c], x[r1][c], x[r2][c], x[r3][c])
    extern __shared__ float sm[];

    const int t = threadIdx.x;
    const long long row0 = (long long)blockIdx.x * ROWS_PER_BLOCK;

    // Per-thread column parameters, resident in registers for the whole block.
    float4   coef[CPT];
    unsigned idxp[CPT];
#pragma unroll
    for (int k = 0; k < CPT; k++) {
        coef[k] = g_coef[t * CPT + k];
        idxp[k] = g_idxp[t * CPT + k];
    }

    // Stage group 0 (interleaved). Coalesced LDG.32 per row, conflict-free STS.128.
    {
        const float* xb = x + row0 * IN_DIM;
        float4* b0 = (float4*)sm;
#pragma unroll
        for (int j = 0; j < 4; j++) {
            int w = t + j * THREADS;
            float4 v;
            v.x = xb[0 * IN_DIM + w];
            v.y = xb[1 * IN_DIM + w];
            v.z = xb[2 * IN_DIM + w];
            v.w = xb[3 * IN_DIM + w];
            b0[w] = v;
        }
    }
    __syncthreads();

    for (int g = 0; g < GROUPS; g++) {
        const char* rw = (const char*)(sm + (g & 1) * (IN_DIM * RG));

        // Prefetch next group into registers (LDG latency overlaps compute).
        float nx[16];
        if (g + 1 < GROUPS) {
            const float* xb = x + (row0 + (long long)(g + 1) * RG) * IN_DIM;
#pragma unroll
            for (int j = 0; j < 4; j++) {
                int w = t + j * THREADS;
#pragma unroll
                for (int r = 0; r < RG; r++)
                    nx[j * 4 + r] = xb[r * IN_DIM + w];
            }
        }

        // Compute 4 columns x 4 rows, in two column-halves to cap register liveness.
#pragma unroll
        for (int h = 0; h < 2; h++) {
            float o[RG][2];
#pragma unroll
            for (int kk = 0; kk < 2; kk++) {
                const int k = h * 2 + kk;
                const unsigned p = idxp[k];
                const float4 a4 = *(const float4*)(rw + ((p & 0xFFFFu) << 4));
                const float4 b4 = *(const float4*)(rw + ((p >> 16) << 4));
                const float4 c = coef[k];
                o[0][kk] = c.x + a4.x * (c.y + c.w * b4.x) + c.z * b4.x;
                o[1][kk] = c.x + a4.y * (c.y + c.w * b4.y) + c.z * b4.y;
                o[2][kk] = c.x + a4.z * (c.y + c.w * b4.z) + c.z * b4.z;
                o[3][kk] = c.x + a4.w * (c.y + c.w * b4.w) + c.z * b4.w;
            }
#pragma unroll
            for (int r = 0; r < RG; r++) {
                float2* yo = (float2*)(y + (row0 + (long long)g * RG + r) * OUT_DIM
                                         + t * CPT + h * 2);
                *yo = make_float2(o[r][0], o[r][1]);
            }
        }

        // Commit next group to the other buffer (conflict-free STS.128).
        if (g + 1 < GROUPS) {
            float4* nb = (float4*)(sm + ((g + 1) & 1) * (IN_DIM * RG));
#pragma unroll
            for (int j = 0; j < 4; j++) {
                int w = t + j * THREADS;
                nb[w] = make_float4(nx[j * 4 + 0], nx[j * 4 + 1],
                                    nx[j * 4 + 2], nx[j * 4 + 3]);
            }
        }
        // One barrier per group: guarantees (a) next buffer fully stored before
        // it is read in iteration g+1, and (b) all reads of buf[g&1] complete
        // before iteration g+1's STS overwrites it (it writes buf[(g+2)&1] = buf[g&1]).
        __syncthreads();
    }
}

extern "C" void kernel_launch(void* const* d_in, const int* in_sizes, int n_in,
                              void* d_out, int out_size)
{
    const float* x  = (const float*)d_in[0];
    const float* w  = (const float*)d_in[1];
    const int*   ia = (const int*)d_in[2];
    const int*   ib = (const int*)d_in[3];
    float*       y  = (float*)d_out;

    // Not a stream operation; safe to call on every launch (incl. during capture).
    cudaFuncSetAttribute(logic_kernel,
                         cudaFuncAttributeMaxDynamicSharedMemorySize, SMEM_BYTES);

    precompute_kernel<<<OUT_DIM / 256, 256>>>(w, ia, ib);
    logic_kernel<<<BATCH / ROWS_PER_BLOCK, THREADS, SMEM_BYTES>>>(x, y);
}

// round 8
// speedup vs baseline: 1.2625x; 1.2625x over previous
#include <cuda_runtime.h>

#define IN_DIM  4096
#define OUT_DIM 4096
#define BATCH   16384
#define THREADS 1024
#define CPT     4              // columns per thread (OUT_DIM / THREADS)
#define RG      2              // rows per group (pair-interleaved in smem)
#define GROUPS  8
#define ROWS_PER_BLOCK (RG * GROUPS)       // 16
#define SMEM_BYTES (2 * IN_DIM * RG * 4)   // double-buffered 2 x 32KB

// Packed per-output-column parameters (filled by precompute kernel)
__device__ float4   g_coef[OUT_DIM];
__device__ unsigned g_idxp[OUT_DIM];   // idx_a | (idx_b << 16)

// GATE_COEFS (16 gates x 4 coefficients)
__constant__ float G[16][4] = {
    {0, 0, 0, 0},  {0, 0, 0, 1},  {0, 1, 0,-1},  {0, 1, 0, 0},
    {0, 0, 1,-1},  {0, 0, 1, 0},  {0, 1, 1,-2},  {0, 1, 1,-1},
    {1,-1,-1, 1},  {1,-1,-1, 2},  {1, 0,-1, 0},  {1, 0,-1, 1},
    {1,-1, 0, 0},  {1,-1, 0, 1},  {1, 0, 0,-1},  {1, 0, 0, 0}
};

// idx buffers may be int32 or int64 depending on the harness's JAX x64 config.
// For int64-encoded indices in [0, IN_DIM), every odd 32-bit word is zero.
// For int32, odd words are random indices (all-zero probability ~ (1/4096)^4).
__device__ __forceinline__ int read_idx(const int* p32, int j, bool is64)
{
    return is64 ? p32[2 * j] : p32[j];
}

__global__ void precompute_kernel(const float* __restrict__ w,
                                  const int* __restrict__ ia32,
                                  const int* __restrict__ ib32)
{
    int j = blockIdx.x * blockDim.x + threadIdx.x;
    if (j >= OUT_DIM) return;

    const bool ia_is64 = ((ia32[1] | ia32[3] | ia32[5] | ia32[7]) == 0);
    const bool ib_is64 = ((ib32[1] | ib32[3] | ib32[5] | ib32[7]) == 0);

    float wv[16];
    float m = -1e30f;
#pragma unroll
    for (int k = 0; k < 16; k++) { wv[k] = w[j * 16 + k]; m = fmaxf(m, wv[k]); }
    float s = 0.f;
#pragma unroll
    for (int k = 0; k < 16; k++) { wv[k] = __expf(wv[k] - m); s += wv[k]; }
    float inv = 1.0f / s;
    float c0 = 0.f, c1 = 0.f, c2 = 0.f, c3 = 0.f;
#pragma unroll
    for (int k = 0; k < 16; k++) {
        float p = wv[k] * inv;
        c0 += p * G[k][0];
        c1 += p * G[k][1];
        c2 += p * G[k][2];
        c3 += p * G[k][3];
    }
    g_coef[j] = make_float4(c0, c1, c2, c3);

    unsigned a = (unsigned)read_idx(ia32, j, ia_is64) & (IN_DIM - 1);
    unsigned b = (unsigned)read_idx(ib32, j, ib_is64) & (IN_DIM - 1);
    g_idxp[j] = a | (b << 16);
}

__global__ __launch_bounds__(THREADS, 1)
void logic_kernel(const float* __restrict__ x, float* __restrict__ y)
{
    // Dynamic smem: two pair-interleaved buffers.
    // Buffer layout: float2 at pair-index c = (x[r0][c], x[r1][c]); byte addr 8c.
    extern __shared__ float sm[];

    const int t = threadIdx.x;
    const long long row0 = (long long)blockIdx.x * ROWS_PER_BLOCK;

    // Per-thread column parameters, resident in registers for the whole block.
    float4   coef[CPT];
    unsigned idxp[CPT];
#pragma unroll
    for (int k = 0; k < CPT; k++) {
        coef[k] = g_coef[t * CPT + k];
        idxp[k] = g_idxp[t * CPT + k];
    }

    // Prefetch group 0 into registers.
    // Thread t owns word-columns {t, t+1024, t+2048, t+3072}; 8 coalesced LDG.32.
    float2 pre[4];
    {
        const float* xb = x + row0 * IN_DIM;
#pragma unroll
        for (int j = 0; j < 4; j++) {
            int w = t + j * THREADS;
            pre[j] = make_float2(xb[w], xb[IN_DIM + w]);
        }
    }

    for (int g = 0; g < GROUPS; g++) {
        const int buf = g & 1;

        // Commit prefetched pair-rows to smem: 4 STS.64, consecutive lanes ->
        // consecutive 8B -> conflict-free.
        {
            float2* nb = (float2*)(sm + buf * (IN_DIM * RG));
#pragma unroll
            for (int j = 0; j < 4; j++)
                nb[t + j * THREADS] = pre[j];
        }

        // Issue next group's global loads early (overlap with compute below).
        if (g + 1 < GROUPS) {
            const float* xb = x + (row0 + (long long)(g + 1) * RG) * IN_DIM;
#pragma unroll
            for (int j = 0; j < 4; j++) {
                int w = t + j * THREADS;
                pre[j] = make_float2(xb[w], xb[IN_DIM + w]);
            }
        }
        __syncthreads();

        // Gather + compute: one LDS.64 per operand covers both rows.
        const char* rw = (const char*)(sm + buf * (IN_DIM * RG));
        float o0[CPT], o1[CPT];
#pragma unroll
        for (int k = 0; k < CPT; k++) {
            const unsigned p = idxp[k];
            const float2 a2 = *(const float2*)(rw + ((p & 0xFFFFu) << 3));
            const float2 b2 = *(const float2*)(rw + ((p >> 16) << 3));
            const float4 c = coef[k];
            o0[k] = c.x + a2.x * (c.y + c.w * b2.x) + c.z * b2.x;
            o1[k] = c.x + a2.y * (c.y + c.w * b2.y) + c.z * b2.y;
        }

        float* yb = y + (row0 + (long long)g * RG) * OUT_DIM + t * CPT;
        *(float4*)yb            = make_float4(o0[0], o0[1], o0[2], o0[3]);
        *(float4*)(yb + OUT_DIM) = make_float4(o1[0], o1[1], o1[2], o1[3]);
        // No trailing sync needed: iteration g+1 writes the *other* buffer, and
        // each warp's sync at g+1 (after these reads in program order) protects
        // this buffer against the overwrite at g+2.
    }
}

extern "C" void kernel_launch(void* const* d_in, const int* in_sizes, int n_in,
                              void* d_out, int out_size)
{
    const float* x  = (const float*)d_in[0];
    const float* w  = (const float*)d_in[1];
    const int*   ia = (const int*)d_in[2];
    const int*   ib = (const int*)d_in[3];
    float*       y  = (float*)d_out;

    // Not a stream operation; safe to call on every launch (incl. during capture).
    cudaFuncSetAttribute(logic_kernel,
                         cudaFuncAttributeMaxDynamicSharedMemorySize, SMEM_BYTES);

    precompute_kernel<<<OUT_DIM / 256, 256>>>(w, ia, ib);
    logic_kernel<<<BATCH / ROWS_PER_BLOCK, THREADS, SMEM_BYTES>>>(x, y);
}

// round 10
// speedup vs baseline: 1.4564x; 1.1536x over previous
#include <cuda_runtime.h>

#define IN_DIM  4096
#define OUT_DIM 4096
#define BATCH   16384
#define THREADS 1024
#define CPT     4              // columns per thread (OUT_DIM / THREADS)
#define RPI     2              // rows per iteration (two independent buffers)
#define ITERS   8
#define ROWS_PER_BLOCK (RPI * ITERS)       // 16
#define SMEM_BYTES (2 * RPI * IN_DIM * 4)  // ping-pong pairs: 4 x 16KB = 64KB

// Packed per-output-column parameters (filled by precompute kernel)
__device__ float4   g_coef[OUT_DIM];
__device__ unsigned g_idxp[OUT_DIM];   // idx_a | (idx_b << 16)

// GATE_COEFS (16 gates x 4 coefficients)
__constant__ float G[16][4] = {
    {0, 0, 0, 0},  {0, 0, 0, 1},  {0, 1, 0,-1},  {0, 1, 0, 0},
    {0, 0, 1,-1},  {0, 0, 1, 0},  {0, 1, 1,-2},  {0, 1, 1,-1},
    {1,-1,-1, 1},  {1,-1,-1, 2},  {1, 0,-1, 0},  {1, 0,-1, 1},
    {1,-1, 0, 0},  {1,-1, 0, 1},  {1, 0, 0,-1},  {1, 0, 0, 0}
};

// idx buffers may be int32 or int64 depending on the harness's JAX x64 config.
// For int64-encoded indices in [0, IN_DIM), every odd 32-bit word is zero.
// For int32, odd words are random indices (all-zero probability ~ (1/4096)^4).
__device__ __forceinline__ int read_idx(const int* p32, int j, bool is64)
{
    return is64 ? p32[2 * j] : p32[j];
}

__global__ void precompute_kernel(const float* __restrict__ w,
                                  const int* __restrict__ ia32,
                                  const int* __restrict__ ib32)
{
    int j = blockIdx.x * blockDim.x + threadIdx.x;
    if (j >= OUT_DIM) return;

    const bool ia_is64 = ((ia32[1] | ia32[3] | ia32[5] | ia32[7]) == 0);
    const bool ib_is64 = ((ib32[1] | ib32[3] | ib32[5] | ib32[7]) == 0);

    float wv[16];
    float m = -1e30f;
#pragma unroll
    for (int k = 0; k < 16; k++) { wv[k] = w[j * 16 + k]; m = fmaxf(m, wv[k]); }
    float s = 0.f;
#pragma unroll
    for (int k = 0; k < 16; k++) { wv[k] = __expf(wv[k] - m); s += wv[k]; }
    float inv = 1.0f / s;
    float c0 = 0.f, c1 = 0.f, c2 = 0.f, c3 = 0.f;
#pragma unroll
    for (int k = 0; k < 16; k++) {
        float p = wv[k] * inv;
        c0 += p * G[k][0];
        c1 += p * G[k][1];
        c2 += p * G[k][2];
        c3 += p * G[k][3];
    }
    g_coef[j] = make_float4(c0, c1, c2, c3);

    unsigned a = (unsigned)read_idx(ia32, j, ia_is64) & (IN_DIM - 1);
    unsigned b = (unsigned)read_idx(ib32, j, ib_is64) & (IN_DIM - 1);
    g_idxp[j] = a | (b << 16);
}

__global__ __launch_bounds__(THREADS, 1)
void logic_kernel(const float* __restrict__ x, float* __restrict__ y)
{
    // Dynamic smem: two ping-pong PAIRS of plain row buffers.
    // pair p at sm + p*2*IN_DIM holds rows {2g, 2g+1} for iterations with g&1==p.
    extern __shared__ float sm[];

    const int t = threadIdx.x;
    const int row0 = blockIdx.x * ROWS_PER_BLOCK;   // fits in int

    // Per-thread column parameters, resident in registers for the whole block.
    float4   coef[CPT];
    unsigned idxp[CPT];
#pragma unroll
    for (int k = 0; k < CPT; k++) {
        coef[k] = g_coef[t * CPT + k];
        idxp[k] = g_idxp[t * CPT + k];
    }

    // Prefetch iteration 0's two rows (coalesced LDG.128: 1024 float4 per row).
    float4 preA, preB;
    {
        const float4* xr = (const float4*)(x + (size_t)row0 * IN_DIM);
        preA = xr[t];                       // row 2g
        preB = xr[t + IN_DIM / 4];          // row 2g+1
    }

    for (int g = 0; g < ITERS; g++) {
        float* pair = sm + (g & 1) * (RPI * IN_DIM);

        // Commit prefetched rows (conflict-free STS.128).
        ((float4*)pair)[t]                = preA;
        ((float4*)(pair + IN_DIM))[t]     = preB;

        // Issue next iteration's global loads early (overlap with compute).
        if (g + 1 < ITERS) {
            const float4* xn = (const float4*)(x + (size_t)(row0 + (g + 1) * RPI) * IN_DIM);
            preA = xn[t];
            preB = xn[t + IN_DIM / 4];
        }
        __syncthreads();

        // Gather + compute: 16 independent LDS.32 chains for latency hiding.
        const float* rA = pair;
        const float* rB = pair + IN_DIM;
        float o0[CPT], o1[CPT];
#pragma unroll
        for (int k = 0; k < CPT; k++) {
            const unsigned ai = idxp[k] & 0xFFFFu;
            const unsigned bi = idxp[k] >> 16;
            const float a0 = rA[ai], b0 = rA[bi];
            const float a1 = rB[ai], b1 = rB[bi];
            const float4 c = coef[k];
            o0[k] = c.x + a0 * (c.y + c.w * b0) + c.z * b0;
            o1[k] = c.x + a1 * (c.y + c.w * b1) + c.z * b1;
        }

        float* yb = y + (size_t)(row0 + g * RPI) * OUT_DIM + t * CPT;
        *(float4*)yb             = make_float4(o0[0], o0[1], o0[2], o0[3]);
        *(float4*)(yb + OUT_DIM) = make_float4(o1[0], o1[1], o1[2], o1[3]);
        // No trailing sync needed: iteration g+1 writes the *other* pair, and
        // each warp's sync at g+1 (after these reads in program order) protects
        // this pair against the overwrite at g+2.
    }
}

extern "C" void kernel_launch(void* const* d_in, const int* in_sizes, int n_in,
                              void* d_out, int out_size)
{
    const float* x  = (const float*)d_in[0];
    const float* w  = (const float*)d_in[1];
    const int*   ia = (const int*)d_in[2];
    const int*   ib = (const int*)d_in[3];
    float*       y  = (float*)d_out;

    // Not a stream operation; safe to call on every launch (incl. during capture).
    cudaFuncSetAttribute(logic_kernel,
                         cudaFuncAttributeMaxDynamicSharedMemorySize, SMEM_BYTES);

    precompute_kernel<<<OUT_DIM / 256, 256>>>(w, ia, ib);
    logic_kernel<<<BATCH / ROWS_PER_BLOCK, THREADS, SMEM_BYTES>>>(x, y);
}

// round 14
// speedup vs baseline: 1.5230x; 1.0458x over previous
#include <cuda_runtime.h>

#define IN_DIM  4096
#define OUT_DIM 4096
#define BATCH   16384
#define THREADS 512
#define CPT     8              // columns per thread: {4t+k} and {2048+4t+k}
#define RPI     2              // rows per iteration
#define ITERS   8
#define NBUF    3              // cp.async ring depth
#define ROWS_PER_BLOCK (RPI * ITERS)                 // 16
#define SMEM_BYTES (NBUF * RPI * IN_DIM * 4)         // 96 KB per CTA

// Packed per-output-column parameters (filled by precompute kernel)
__device__ float4   g_coef[OUT_DIM];
__device__ unsigned g_idxp[OUT_DIM];   // idx_a | (idx_b << 16)

// GATE_COEFS (16 gates x 4 coefficients)
__constant__ float G[16][4] = {
    {0, 0, 0, 0},  {0, 0, 0, 1},  {0, 1, 0,-1},  {0, 1, 0, 0},
    {0, 0, 1,-1},  {0, 0, 1, 0},  {0, 1, 1,-2},  {0, 1, 1,-1},
    {1,-1,-1, 1},  {1,-1,-1, 2},  {1, 0,-1, 0},  {1, 0,-1, 1},
    {1,-1, 0, 0},  {1,-1, 0, 1},  {1, 0, 0,-1},  {1, 0, 0, 0}
};

// idx buffers may be int32 or int64 depending on the harness's JAX x64 config.
// For int64-encoded indices in [0, IN_DIM), every odd 32-bit word is zero.
// For int32, odd words are random indices (all-zero probability ~ (1/4096)^4).
__device__ __forceinline__ int read_idx(const int* p32, int j, bool is64)
{
    return is64 ? p32[2 * j] : p32[j];
}

__global__ void precompute_kernel(const float* __restrict__ w,
                                  const int* __restrict__ ia32,
                                  const int* __restrict__ ib32)
{
    int j = blockIdx.x * blockDim.x + threadIdx.x;
    if (j >= OUT_DIM) return;

    const bool ia_is64 = ((ia32[1] | ia32[3] | ia32[5] | ia32[7]) == 0);
    const bool ib_is64 = ((ib32[1] | ib32[3] | ib32[5] | ib32[7]) == 0);

    float wv[16];
    float m = -1e30f;
#pragma unroll
    for (int k = 0; k < 16; k++) { wv[k] = w[j * 16 + k]; m = fmaxf(m, wv[k]); }
    float s = 0.f;
#pragma unroll
    for (int k = 0; k < 16; k++) { wv[k] = __expf(wv[k] - m); s += wv[k]; }
    float inv = 1.0f / s;
    float c0 = 0.f, c1 = 0.f, c2 = 0.f, c3 = 0.f;
#pragma unroll
    for (int k = 0; k < 16; k++) {
        float p = wv[k] * inv;
        c0 += p * G[k][0];
        c1 += p * G[k][1];
        c2 += p * G[k][2];
        c3 += p * G[k][3];
    }
    g_coef[j] = make_float4(c0, c1, c2, c3);

    unsigned a = (unsigned)read_idx(ia32, j, ia_is64) & (IN_DIM - 1);
    unsigned b = (unsigned)read_idx(ib32, j, ib_is64) & (IN_DIM - 1);
    g_idxp[j] = a | (b << 16);
}

__device__ __forceinline__ void cp_async16(unsigned s_addr, const void* g_addr)
{
    asm volatile("cp.async.cg.shared.global [%0], [%1], 16;"
                 :: "r"(s_addr), "l"(g_addr));
}
__device__ __forceinline__ void cp_commit()
{
    asm volatile("cp.async.commit_group;");
}

__global__ __launch_bounds__(THREADS, 2)
void logic_kernel(const float* __restrict__ x, float* __restrict__ y)
{
    // 3-stage ring of 2-row buffers, filled by cp.async (no RF round trip).
    extern __shared__ float sm[];

    const int t = threadIdx.x;
    const int row0 = blockIdx.x * ROWS_PER_BLOCK;

    // Per-thread column parameters, resident in registers for the whole block.
    // Columns: k<4 -> 4t+k (contiguous), k>=4 -> 2048+4t+(k-4) (contiguous).
    float4   coef[CPT];
    unsigned idxp[CPT];
#pragma unroll
    for (int k = 0; k < 4; k++) {
        coef[k]     = g_coef[4 * t + k];
        idxp[k]     = g_idxp[4 * t + k];
        coef[k + 4] = g_coef[2048 + 4 * t + k];
        idxp[k + 4] = g_idxp[2048 + 4 * t + k];
    }

    const unsigned smem_base = (unsigned)__cvta_generic_to_shared(sm);

    // Stage iteration g's RPI rows into ring slot g%NBUF (4 x cp.async.16).
    auto stage = [&](int g) {
        const unsigned dst = smem_base + (unsigned)((g % NBUF) * (RPI * IN_DIM) * 4);
        const float* src = x + (size_t)(row0 + g * RPI) * IN_DIM;
#pragma unroll
        for (int r = 0; r < RPI; r++) {
#pragma unroll
            for (int c = 0; c < 2; c++) {
                const int w4 = (t + c * THREADS) * 4;     // float index, 16B aligned
                cp_async16(dst + (unsigned)((r * IN_DIM + w4) * 4),
                           src + (size_t)r * IN_DIM + w4);
            }
        }
        cp_commit();
    };

    stage(0);
    stage(1);

    for (int g = 0; g < ITERS; g++) {
        // Ensure slot g%NBUF is complete: allow only the newest group pending.
        if (g < ITERS - 1) asm volatile("cp.async.wait_group 1;");
        else               asm volatile("cp.async.wait_group 0;");
        __syncthreads();   // all warps past compute(g-1); slot data visible to all

        // Refill slot (g+2)%NBUF — last read at iteration g-1, protected by the
        // barrier above. Issued before compute so the copy overlaps the gather.
        if (g + 2 < ITERS) stage(g + 2);

        const float* rw = sm + (g % NBUF) * (RPI * IN_DIM);
#pragma unroll
        for (int r = 0; r < RPI; r++) {
            const float* row = rw + r * IN_DIM;
#pragma unroll
            for (int h = 0; h < 2; h++) {
                float o[4];
#pragma unroll
                for (int k = 0; k < 4; k++) {
                    const unsigned p = idxp[h * 4 + k];
                    const float a = row[p & 0xFFFFu];
                    const float b = row[p >> 16];
                    const float4 c = coef[h * 4 + k];
                    o[k] = c.x + a * (c.y + c.w * b) + c.z * b;
                }
                float* yb = y + (size_t)(row0 + g * RPI + r) * OUT_DIM
                              + h * 2048 + 4 * t;
                *(float4*)yb = make_float4(o[0], o[1], o[2], o[3]);
            }
        }
        // No trailing barrier: the next iteration's leading __syncthreads()
        // orders these reads before any refill of this slot (g+3 targets
        // (g+3)%NBUF != (g)%NBUF; slot g%NBUF is next written at g+3 via the
        // stage() call at iteration g+1, which follows that barrier).
    }
}

extern "C" void kernel_launch(void* const* d_in, const int* in_sizes, int n_in,
                              void* d_out, int out_size)
{
    const float* x  = (const float*)d_in[0];
    const float* w  = (const float*)d_in[1];
    const int*   ia = (const int*)d_in[2];
    const int*   ib = (const int*)d_in[3];
    float*       y  = (float*)d_out;

    // Not a stream operation; safe to call on every launch (incl. during capture).
    cudaFuncSetAttribute(logic_kernel,
                         cudaFuncAttributeMaxDynamicSharedMemorySize, SMEM_BYTES);

    precompute_kernel<<<OUT_DIM / 256, 256>>>(w, ia, ib);
    logic_kernel<<<BATCH / ROWS_PER_BLOCK, THREADS, SMEM_BYTES>>>(x, y);
}

// round 16
// speedup vs baseline: 1.5425x; 1.0128x over previous
#include <cuda_runtime.h>

#define IN_DIM  4096
#define OUT_DIM 4096
#define BATCH   16384
#define THREADS 512
#define CPT     8              // columns per thread: {4t+k} and {2048+4t+k}
#define RPI     2              // rows per iteration (one pair)
#define NBUF    3              // cp.async ring depth
#define NBLK    296            // 148 SMs x 2 resident CTAs: exactly one wave
#define PAIRS   (BATCH / RPI)  // 8192 row-pairs total
#define SMEM_BYTES (NBUF * RPI * IN_DIM * 4)         // 96 KB per CTA

// Packed per-output-column parameters (filled by precompute kernel)
__device__ float4   g_coef[OUT_DIM];
__device__ unsigned g_idxp[OUT_DIM];   // idx_a | (idx_b << 16)

// GATE_COEFS (16 gates x 4 coefficients)
__constant__ float G[16][4] = {
    {0, 0, 0, 0},  {0, 0, 0, 1},  {0, 1, 0,-1},  {0, 1, 0, 0},
    {0, 0, 1,-1},  {0, 0, 1, 0},  {0, 1, 1,-2},  {0, 1, 1,-1},
    {1,-1,-1, 1},  {1,-1,-1, 2},  {1, 0,-1, 0},  {1, 0,-1, 1},
    {1,-1, 0, 0},  {1,-1, 0, 1},  {1, 0, 0,-1},  {1, 0, 0, 0}
};

// idx buffers may be int32 or int64 depending on the harness's JAX x64 config.
// For int64-encoded indices in [0, IN_DIM), every odd 32-bit word is zero.
// For int32, odd words are random indices (all-zero probability ~ (1/4096)^4).
__device__ __forceinline__ int read_idx(const int* p32, int j, bool is64)
{
    return is64 ? p32[2 * j] : p32[j];
}

__global__ void precompute_kernel(const float* __restrict__ w,
                                  const int* __restrict__ ia32,
                                  const int* __restrict__ ib32)
{
    int j = blockIdx.x * blockDim.x + threadIdx.x;
    if (j >= OUT_DIM) return;

    const bool ia_is64 = ((ia32[1] | ia32[3] | ia32[5] | ia32[7]) == 0);
    const bool ib_is64 = ((ib32[1] | ib32[3] | ib32[5] | ib32[7]) == 0);

    float wv[16];
    float m = -1e30f;
#pragma unroll
    for (int k = 0; k < 16; k++) { wv[k] = w[j * 16 + k]; m = fmaxf(m, wv[k]); }
    float s = 0.f;
#pragma unroll
    for (int k = 0; k < 16; k++) { wv[k] = __expf(wv[k] - m); s += wv[k]; }
    float inv = 1.0f / s;
    float c0 = 0.f, c1 = 0.f, c2 = 0.f, c3 = 0.f;
#pragma unroll
    for (int k = 0; k < 16; k++) {
        float p = wv[k] * inv;
        c0 += p * G[k][0];
        c1 += p * G[k][1];
        c2 += p * G[k][2];
        c3 += p * G[k][3];
    }
    g_coef[j] = make_float4(c0, c1, c2, c3);

    unsigned a = (unsigned)read_idx(ia32, j, ia_is64) & (IN_DIM - 1);
    unsigned b = (unsigned)read_idx(ib32, j, ib_is64) & (IN_DIM - 1);
    g_idxp[j] = a | (b << 16);
}

__device__ __forceinline__ void cp_async16(unsigned s_addr, const void* g_addr)
{
    asm volatile("cp.async.cg.shared.global [%0], [%1], 16;"
                 :: "r"(s_addr), "l"(g_addr));
}
__device__ __forceinline__ void cp_commit()
{
    asm volatile("cp.async.commit_group;");
}

__global__ __launch_bounds__(THREADS, 2)
void logic_kernel(const float* __restrict__ x, float* __restrict__ y)
{
    // 3-stage ring of 2-row buffers, filled by cp.async (no RF round trip).
    extern __shared__ float sm[];

    const int t = threadIdx.x;

    // Persistent block: statically owns a contiguous span of row-pairs.
    // PAIRS = 8192 over NBLK = 296 blocks: first 200 blocks get 28, rest 27.
    const int bid  = blockIdx.x;
    const int q    = PAIRS / NBLK;            // 27
    const int r    = PAIRS % NBLK;            // 200
    const int base = bid * q + (bid < r ? bid : r);
    const int np   = q + (bid < r ? 1 : 0);   // pairs this block owns (27/28)

    // Per-thread column parameters, resident in registers for the whole block.
    // Columns: k<4 -> 4t+k (contiguous), k>=4 -> 2048+4t+(k-4) (contiguous).
    float4   coef[CPT];
    unsigned idxp[CPT];
#pragma unroll
    for (int k = 0; k < 4; k++) {
        coef[k]     = g_coef[4 * t + k];
        idxp[k]     = g_idxp[4 * t + k];
        coef[k + 4] = g_coef[2048 + 4 * t + k];
        idxp[k + 4] = g_idxp[2048 + 4 * t + k];
    }

    const unsigned smem_base = (unsigned)__cvta_generic_to_shared(sm);

    // Stage local pair g into ring slot g%NBUF (4 x cp.async.16 per thread).
    auto stage = [&](int g) {
        const unsigned dst = smem_base + (unsigned)((g % NBUF) * (RPI * IN_DIM) * 4);
        const float* src = x + (size_t)(base + g) * RPI * IN_DIM;
#pragma unroll
        for (int rr = 0; rr < RPI; rr++) {
#pragma unroll
            for (int c = 0; c < 2; c++) {
                const int w4 = (t + c * THREADS) * 4;     // float index, 16B aligned
                cp_async16(dst + (unsigned)((rr * IN_DIM + w4) * 4),
                           src + (size_t)rr * IN_DIM + w4);
            }
        }
        cp_commit();
    };

    stage(0);
    if (np > 1) stage(1);

    for (int g = 0; g < np; g++) {
        // Ensure slot g%NBUF is complete: allow only the newest group pending.
        if (g < np - 1) asm volatile("cp.async.wait_group 1;");
        else            asm volatile("cp.async.wait_group 0;");
        __syncthreads();   // all warps past compute(g-1); slot data visible to all

        // Refill slot (g+2)%NBUF — last read at iteration g-1, protected by the
        // barrier above. Issued before compute so the copy overlaps the gather.
        if (g + 2 < np) stage(g + 2);

        const float* rw = sm + (g % NBUF) * (RPI * IN_DIM);
#pragma unroll
        for (int rr = 0; rr < RPI; rr++) {
            const float* row = rw + rr * IN_DIM;
#pragma unroll
            for (int h = 0; h < 2; h++) {
                float o[4];
#pragma unroll
                for (int k = 0; k < 4; k++) {
                    const unsigned p = idxp[h * 4 + k];
                    const float a = row[p & 0xFFFFu];
                    const float b = row[p >> 16];
                    const float4 c = coef[h * 4 + k];
                    o[k] = c.x + a * (c.y + c.w * b) + c.z * b;
                }
                float* yb = y + (size_t)((base + g) * RPI + rr) * OUT_DIM
                              + h * 2048 + 4 * t;
                *(float4*)yb = make_float4(o[0], o[1], o[2], o[3]);
            }
        }
        // No trailing barrier: the next iteration's leading __syncthreads()
        // orders these reads before any refill of this slot (the slot is next
        // written by the stage() call at iteration g+1, which follows that
        // barrier in every warp's program order).
    }
}

extern "C" void kernel_launch(void* const* d_in, const int* in_sizes, int n_in,
                              void* d_out, int out_size)
{
    const float* x  = (const float*)d_in[0];
    const float* w  = (const float*)d_in[1];
    const int*   ia = (const int*)d_in[2];
    const int*   ib = (const int*)d_in[3];
    float*       y  = (float*)d_out;

    // Not a stream operation; safe to call on every launch (incl. during capture).
    cudaFuncSetAttribute(logic_kernel,
                         cudaFuncAttributeMaxDynamicSharedMemorySize, SMEM_BYTES);

    precompute_kernel<<<OUT_DIM / 256, 256>>>(w, ia, ib);
    logic_kernel<<<NBLK, THREADS, SMEM_BYTES>>>(x, y);
}

// round 17
// speedup vs baseline: 1.5803x; 1.0245x over previous
#include <cuda_runtime.h>

#define IN_DIM  4096
#define OUT_DIM 4096
#define BATCH   16384
#define THREADS 512
#define NWARPS  (THREADS / 32)
#define CPT     8              // columns per thread: {4t+k} and {2048+4t+k}
#define RPI     2              // rows per iteration (one contiguous pair)
#define NBUF    3              // ring depth
#define NBLK    296            // 148 SMs x 2 resident CTAs: one persistent wave
#define PAIRS   (BATCH / RPI)  // 8192 row-pairs total
#define SLOT_FLOATS (RPI * IN_DIM)
#define SLOT_BYTES  (SLOT_FLOATS * 4)                  // 32 KB
#define SMEM_BYTES  (NBUF * SLOT_BYTES + 64)           // slots + mbarriers

// Packed per-output-column parameters (filled by precompute kernel)
__device__ float4   g_coef[OUT_DIM];
__device__ unsigned g_idxp[OUT_DIM];   // idx_a | (idx_b << 16)

// GATE_COEFS (16 gates x 4 coefficients)
__constant__ float G[16][4] = {
    {0, 0, 0, 0},  {0, 0, 0, 1},  {0, 1, 0,-1},  {0, 1, 0, 0},
    {0, 0, 1,-1},  {0, 0, 1, 0},  {0, 1, 1,-2},  {0, 1, 1,-1},
    {1,-1,-1, 1},  {1,-1,-1, 2},  {1, 0,-1, 0},  {1, 0,-1, 1},
    {1,-1, 0, 0},  {1,-1, 0, 1},  {1, 0, 0,-1},  {1, 0, 0, 0}
};

// idx buffers may be int32 or int64 depending on the harness's JAX x64 config.
// For int64-encoded indices in [0, IN_DIM), every odd 32-bit word is zero.
// For int32, odd words are random indices (all-zero probability ~ (1/4096)^4).
__device__ __forceinline__ int read_idx(const int* p32, int j, bool is64)
{
    return is64 ? p32[2 * j] : p32[j];
}

__global__ void precompute_kernel(const float* __restrict__ w,
                                  const int* __restrict__ ia32,
                                  const int* __restrict__ ib32)
{
    int j = blockIdx.x * blockDim.x + threadIdx.x;
    if (j >= OUT_DIM) return;

    const bool ia_is64 = ((ia32[1] | ia32[3] | ia32[5] | ia32[7]) == 0);
    const bool ib_is64 = ((ib32[1] | ib32[3] | ib32[5] | ib32[7]) == 0);

    float wv[16];
    float m = -1e30f;
#pragma unroll
    for (int k = 0; k < 16; k++) { wv[k] = w[j * 16 + k]; m = fmaxf(m, wv[k]); }
    float s = 0.f;
#pragma unroll
    for (int k = 0; k < 16; k++) { wv[k] = __expf(wv[k] - m); s += wv[k]; }
    float inv = 1.0f / s;
    float c0 = 0.f, c1 = 0.f, c2 = 0.f, c3 = 0.f;
#pragma unroll
    for (int k = 0; k < 16; k++) {
        float p = wv[k] * inv;
        c0 += p * G[k][0];
        c1 += p * G[k][1];
        c2 += p * G[k][2];
        c3 += p * G[k][3];
    }
    g_coef[j] = make_float4(c0, c1, c2, c3);

    unsigned a = (unsigned)read_idx(ia32, j, ia_is64) & (IN_DIM - 1);
    unsigned b = (unsigned)read_idx(ib32, j, ib_is64) & (IN_DIM - 1);
    g_idxp[j] = a | (b << 16);
}

// ---- mbarrier / bulk-copy primitives ---------------------------------------

__device__ __forceinline__ void mbar_init(unsigned addr, unsigned count)
{
    asm volatile("mbarrier.init.shared.b64 [%0], %1;" :: "r"(addr), "r"(count)
                 : "memory");
}
__device__ __forceinline__ void mbar_expect_tx(unsigned addr, unsigned bytes)
{
    asm volatile("mbarrier.arrive.expect_tx.shared.b64 _, [%0], %1;"
                 :: "r"(addr), "r"(bytes) : "memory");
}
__device__ __forceinline__ void mbar_arrive(unsigned addr)
{
    asm volatile("mbarrier.arrive.shared::cta.b64 _, [%0];" :: "r"(addr)
                 : "memory");
}
__device__ __forceinline__ void mbar_wait(unsigned addr, unsigned parity)
{
    asm volatile(
        "{\n\t.reg .pred P;\n\t"
        "WL_%=:\n\t"
        "mbarrier.try_wait.parity.acquire.cta.shared::cta.b64 P, [%0], %1, 0x989680;\n\t"
        "@P bra.uni WD_%=;\n\t"
        "bra.uni WL_%=;\n\t"
        "WD_%=:\n\t}"
        :: "r"(addr), "r"(parity) : "memory");
}
__device__ __forceinline__ void bulk_g2s(unsigned dst, const void* src,
                                         unsigned bytes, unsigned mbar)
{
    asm volatile(
        "cp.async.bulk.shared::cta.global.mbarrier::complete_tx::bytes "
        "[%0], [%1], %2, [%3];"
        :: "r"(dst), "l"(src), "r"(bytes), "r"(mbar) : "memory");
}

// ----------------------------------------------------------------------------

__global__ __launch_bounds__(THREADS, 2)
void logic_kernel(const float* __restrict__ x, float* __restrict__ y)
{
    extern __shared__ float sm[];   // [NBUF * SLOT_FLOATS] data, then mbarriers

    const int t    = threadIdx.x;
    const int lane = t & 31;

    // Persistent block: statically owns a contiguous span of row-pairs.
    const int bid  = blockIdx.x;
    const int q    = PAIRS / NBLK;            // 27
    const int r    = PAIRS % NBLK;            // 200
    const int base = bid * q + (bid < r ? bid : r);
    const int np   = q + (bid < r ? 1 : 0);   // 27 or 28 (always >= NBUF)

    const unsigned smem_base = (unsigned)__cvta_generic_to_shared(sm);
    const unsigned mb_full0  = smem_base + NBUF * SLOT_BYTES;   // full[0..2]
    const unsigned mb_empty0 = mb_full0 + NBUF * 8;             // empty[0..2]

    if (t == 0) {
#pragma unroll
        for (int s = 0; s < NBUF; s++) {
            mbar_init(mb_full0  + s * 8, 1);        // expect_tx arrive
            mbar_init(mb_empty0 + s * 8, NWARPS);   // one arrive per warp
        }
    }
    __syncthreads();   // mbarriers visible to all threads before any use

    // Per-thread column parameters, resident in registers for the whole block.
    float4   coef[CPT];
    unsigned idxp[CPT];
#pragma unroll
    for (int k = 0; k < 4; k++) {
        coef[k]     = g_coef[4 * t + k];
        idxp[k]     = g_idxp[4 * t + k];
        coef[k + 4] = g_coef[2048 + 4 * t + k];
        idxp[k + 4] = g_idxp[2048 + 4 * t + k];
    }

    // Producer prologue: fill all NBUF slots (np >= 3 always).
    if (t == 0) {
#pragma unroll
        for (int g = 0; g < NBUF; g++) {
            mbar_expect_tx(mb_full0 + g * 8, SLOT_BYTES);
            bulk_g2s(smem_base + g * SLOT_BYTES,
                     x + (size_t)(base + g) * SLOT_FLOATS,
                     SLOT_BYTES, mb_full0 + g * 8);
        }
    }

    // Consumer cursor (all threads) and producer empty-cursor (tid 0 only).
    int cs = 0, cph = 0;    // consumer: slot, full-parity
    int pph = 0;            // producer: empty-parity for reuse n>=1

    for (int g = 0; g < np; g++) {
        // Wait for slot data (flips when the bulk copy lands; independent of
        // other warps' compute — fast warps run ahead).
        mbar_wait(mb_full0 + cs * 8, cph);

        const float* rw = sm + cs * SLOT_FLOATS;
#pragma unroll
        for (int rr = 0; rr < RPI; rr++) {
            const float* row = rw + rr * IN_DIM;
#pragma unroll
            for (int h = 0; h < 2; h++) {
                float o[4];
#pragma unroll
                for (int k = 0; k < 4; k++) {
                    const unsigned p = idxp[h * 4 + k];
                    const float a = row[p & 0xFFFFu];
                    const float b = row[p >> 16];
                    const float4 c = coef[h * 4 + k];
                    o[k] = c.x + a * (c.y + c.w * b) + c.z * b;
                }
                float* yb = y + (size_t)((base + g) * RPI + rr) * OUT_DIM
                              + h * 2048 + 4 * t;
                *(float4*)yb = make_float4(o[0], o[1], o[2], o[3]);
            }
        }

        // Signal this warp is done reading slot cs.
        __syncwarp();
        if (lane == 0) mbar_arrive(mb_empty0 + cs * 8);

        // Producer: refill this slot for iteration g+NBUF. Only tid 0 blocks
        // on the block-wide empty completion; all other warps roll on.
        if (t == 0 && g + NBUF < np) {
            mbar_wait(mb_empty0 + cs * 8, pph);
            mbar_expect_tx(mb_full0 + cs * 8, SLOT_BYTES);
            bulk_g2s(smem_base + cs * SLOT_BYTES,
                     x + (size_t)(base + g + NBUF) * SLOT_FLOATS,
                     SLOT_BYTES, mb_full0 + cs * 8);
            if (cs == NBUF - 1) pph ^= 1;
        }

        if (++cs == NBUF) { cs = 0; cph ^= 1; }
    }
}

extern "C" void kernel_launch(void* const* d_in, const int* in_sizes, int n_in,
                              void* d_out, int out_size)
{
    const float* x  = (const float*)d_in[0];
    const float* w  = (const float*)d_in[1];
    const int*   ia = (const int*)d_in[2];
    const int*   ib = (const int*)d_in[3];
    float*       y  = (float*)d_out;

    // Not a stream operation; safe to call on every launch (incl. during capture).
    cudaFuncSetAttribute(logic_kernel,
                         cudaFuncAttributeMaxDynamicSharedMemorySize, SMEM_BYTES);

    precompute_kernel<<<OUT_DIM / 256, 256>>>(w, ia, ib);
    logic_kernel<<<NBLK, THREADS, SMEM_BYTES>>>(x, y);
}